// round 12
// baseline (speedup 1.0000x reference)
#include <cuda_runtime.h>
#include <cuda_fp16.h>
#include <math.h>
#include <stdint.h>

#define NPIX   65536      // 256*256
#define PCOUNT 1024       // 4 * 16 * 16 patches
#define NB     512        // 8^3 bins
#define SINK_EPS 1e-6f

// sink kernel smem: 230400 bytes dynamic
#define SINK_SMEM_BYTES 230400
#define SINK_SMEM_WORDS (SINK_SMEM_BYTES / 4)   // 57600
#define AUX_WORDS 5632                          // u,v,hrw,htw,idr,idt(1536) + part(4096)
#define SCAP_F32 (SINK_SMEM_WORDS - AUX_WORDS)  // 51968 floats for S

// ---------------- scratch (static device globals; no allocation) ----------------
__device__ float    g_oklab[2][4 * 3 * NPIX];
__device__ unsigned g_mm[12];
__device__ float    g_K[NB * NB];
__device__ float    g_KC[NB * NB];
__device__ int      g_scnt[2][PCOUNT];
__device__ int      g_sidx[2][PCOUNT][256];
__device__ float    g_sw[2][PCOUNT][256];
__device__ float    g_emd[PCOUNT];

// ---------------- helpers ----------------
__device__ __forceinline__ unsigned fenc(float f) {
    unsigned u = __float_as_uint(f);
    return (u & 0x80000000u) ? ~u : (u | 0x80000000u);
}
__device__ __forceinline__ float fdec(unsigned u) {
    return __uint_as_float((u & 0x80000000u) ? (u ^ 0x80000000u) : ~u);
}
__device__ __forceinline__ float srgb_lin(float x) {
    x = fminf(fmaxf(x, 0.0f), 1.0f);
    return (x <= 0.04045f) ? x * (1.0f / 12.92f)
                           : powf((x + 0.055f) * (1.0f / 1.055f), 2.4f);
}
__device__ __forceinline__ void get_lohi(int img, float* lo, float* hi) {
#pragma unroll
    for (int c = 0; c < 3; c++) {
        float l = fdec(g_mm[img * 3 + c]) - 0.01f;
        float h = fdec(g_mm[6 + img * 3 + c]) + 0.01f;
        if (h - l < 1e-4f) { l -= 0.05f; h += 0.05f; }
        lo[c] = l; hi[c] = h;
    }
}

// ---------------- init: minmax sentinels ----------------
__global__ void init_kernel() {
    int idx = threadIdx.x;
    if (idx < 6) g_mm[idx] = 0xFFFFFFFFu;
    else if (idx < 12) g_mm[idx] = 0u;
}

// ---------------- sRGB -> OKLab + per-channel global min/max ----------------
__global__ void oklab_kernel(const float* __restrict__ ref, const float* __restrict__ tgt) {
    const int img = blockIdx.y;
    const float* __restrict__ in = img ? tgt : ref;
    float* __restrict__ outp = g_oklab[img];
    float mn0 = 1e30f, mn1 = 1e30f, mn2 = 1e30f;
    float mx0 = -1e30f, mx1 = -1e30f, mx2 = -1e30f;

    for (int idx = blockIdx.x * blockDim.x + threadIdx.x; idx < 4 * NPIX;
         idx += gridDim.x * blockDim.x) {
        int b = idx >> 16;
        int hw = idx & 65535;
        int base = b * 3 * NPIX + hw;
        float r  = srgb_lin(in[base]);
        float g  = srgb_lin(in[base + NPIX]);
        float bl = srgb_lin(in[base + 2 * NPIX]);
        float l = 0.4122214708f * r + 0.5363325363f * g + 0.0514459929f * bl;
        float m = 0.2119034982f * r + 0.6806995451f * g + 0.1073969566f * bl;
        float s = 0.0883024619f * r + 0.2817188376f * g + 0.6299787005f * bl;
        l = fmaxf(l, 0.0f); m = fmaxf(m, 0.0f); s = fmaxf(s, 0.0f);
        float lg = (l > 0.0f) ? cbrtf(fmaxf(l, 1e-12f)) : 0.0f;
        float mg = (m > 0.0f) ? cbrtf(fmaxf(m, 1e-12f)) : 0.0f;
        float sg = (s > 0.0f) ? cbrtf(fmaxf(s, 1e-12f)) : 0.0f;
        float L = 0.2104542553f * lg + 0.793617785f  * mg - 0.0040720468f * sg;
        float A = 1.9779984951f * lg - 2.428592205f  * mg + 0.4505937099f * sg;
        float B = 0.0259040371f * lg + 0.7827717662f * mg - 0.808675766f  * sg;
        outp[base] = L; outp[base + NPIX] = A; outp[base + 2 * NPIX] = B;
        mn0 = fminf(mn0, L); mx0 = fmaxf(mx0, L);
        mn1 = fminf(mn1, A); mx1 = fmaxf(mx1, A);
        mn2 = fminf(mn2, B); mx2 = fmaxf(mx2, B);
    }
#pragma unroll
    for (int o = 16; o > 0; o >>= 1) {
        mn0 = fminf(mn0, __shfl_down_sync(0xffffffffu, mn0, o));
        mn1 = fminf(mn1, __shfl_down_sync(0xffffffffu, mn1, o));
        mn2 = fminf(mn2, __shfl_down_sync(0xffffffffu, mn2, o));
        mx0 = fmaxf(mx0, __shfl_down_sync(0xffffffffu, mx0, o));
        mx1 = fmaxf(mx1, __shfl_down_sync(0xffffffffu, mx1, o));
        mx2 = fmaxf(mx2, __shfl_down_sync(0xffffffffu, mx2, o));
    }
    if ((threadIdx.x & 31) == 0) {
        atomicMin(&g_mm[img * 3 + 0], fenc(mn0));
        atomicMin(&g_mm[img * 3 + 1], fenc(mn1));
        atomicMin(&g_mm[img * 3 + 2], fenc(mn2));
        atomicMax(&g_mm[6 + img * 3 + 0], fenc(mx0));
        atomicMax(&g_mm[6 + img * 3 + 1], fenc(mx1));
        atomicMax(&g_mm[6 + img * 3 + 2], fenc(mx2));
    }
}

// ---------------- build K = exp(-cost/REG) and KC = K*cost on averaged grid ----------------
__global__ void buildK_kernel() {
    int i = blockIdx.x, j = threadIdx.x;
    float lor[3], hir[3], lot[3], hit[3];
    get_lohi(0, lor, hir);
    get_lohi(1, lot, hit);
    float step[3];
#pragma unroll
    for (int c = 0; c < 3; c++)
        step[c] = ((hir[c] - lor[c]) + (hit[c] - lot[c])) * 0.5f * 0.125f;
    int i0 = i >> 6, i1 = (i >> 3) & 7, i2 = i & 7;
    int j0 = j >> 6, j1 = (j >> 3) & 7, j2 = j & 7;
    float d0 = step[0] * (float)(i0 - j0);
    float d1 = step[1] * (float)(i1 - j1);
    float d2 = step[2] * (float)(i2 - j2);
    float dd = d0 * d0 + d1 * d1 + d2 * d2;
    float cost = (dd > 0.0f) ? sqrtf(dd) : 0.0f;
    float Kv = expf(-cost * 10.0f);        // REG = 0.1
    g_K[i * NB + j]  = Kv;
    g_KC[i * NB + j] = Kv * cost;
}

// ---------------- per-patch histograms + deterministic support-list extraction --------
__global__ void hist_kernel() {
    const int img = blockIdx.y, p = blockIdx.x, t = threadIdx.x;   // 256 threads
    __shared__ float h[NB];
    __shared__ int sca[NB], scb[NB];
    __shared__ float lo_s[3], inv_s[3];
    if (t == 0) {
        float lo[3], hi[3];
        get_lohi(img, lo, hi);
#pragma unroll
        for (int c = 0; c < 3; c++) { lo_s[c] = lo[c]; inv_s[c] = 8.0f / (hi[c] - lo[c]); }
    }
    h[t] = 0.0f; h[t + 256] = 0.0f;
    __syncthreads();

    int b = p >> 8, ph = (p >> 4) & 15, pw = p & 15;
    int py = t >> 4, px = t & 15;
    int hh = (ph << 4) + py, ww = (pw << 4) + px;
    int base = b * 3 * NPIX + hh * 256 + ww;
    const float* ok = g_oklab[img];
    float xL = ok[base], xA = ok[base + NPIX], xB = ok[base + 2 * NPIX];
    int i0 = (int)floorf((xL - lo_s[0]) * inv_s[0]); i0 = min(7, max(0, i0));
    int i1 = (int)floorf((xA - lo_s[1]) * inv_s[1]); i1 = min(7, max(0, i1));
    int i2 = (int)floorf((xB - lo_s[2]) * inv_s[2]); i2 = min(7, max(0, i2));
    atomicAdd(&h[(i0 << 6) | (i1 << 3) | i2], 1.0f);
    __syncthreads();

    // inclusive prefix scan of occupancy flags over 512 bins (Hillis-Steele, ping-pong)
    sca[t] = (h[t] > 0.0f) ? 1 : 0;
    sca[t + 256] = (h[t + 256] > 0.0f) ? 1 : 0;
    __syncthreads();
    int* src = sca; int* dst = scb;
    for (int off = 1; off < NB; off <<= 1) {
#pragma unroll
        for (int q = 0; q < 2; q++) {
            int i = t + q * 256;
            dst[i] = src[i] + ((i >= off) ? src[i - off] : 0);
        }
        __syncthreads();
        int* tmp = src; src = dst; dst = tmp;
    }

#pragma unroll
    for (int q = 0; q < 2; q++) {
        int i = t + q * 256;
        if (h[i] > 0.0f) {
            int pos = src[i] - 1;
            g_sidx[img][p][pos] = i;
            g_sw[img][p][pos]   = h[i] * (1.0f / 256.0f);
        }
    }
    if (t == 0) g_scnt[img][p] = src[NB - 1];
}

// ---------------- per-patch Sinkhorn: all 20 iterations CTA-local over sparse support --
// smem layout (words): u[256] v[256] hrw[256] htw[256] idr[256] idt[256] part[16*256] S[...]
template <typename T>
__device__ void sink_body(float* sm, int p, int sr, int st, int pad) {
    float* u   = sm;
    float* v   = sm + 256;
    float* hrw = sm + 512;
    float* htw = sm + 768;
    int*   idr = (int*)(sm + 1024);
    int*   idt = (int*)(sm + 1280);
    float* part = sm + 1536;              // [16][256]
    T*     S   = (T*)(sm + AUX_WORDS);

    const int tid = threadIdx.x, lane = tid & 31, w = tid >> 5;   // 16 warps

    if (tid < 256) {
        if (tid < sr) { idr[tid] = g_sidx[0][p][tid]; hrw[tid] = g_sw[0][p][tid]; u[tid] = 1.0f; }
        if (tid < st) { idt[tid] = g_sidx[1][p][tid]; htw[tid] = g_sw[1][p][tid]; }
    }
    __syncthreads();

    // gather S[i][j] = K[idr[i], idt[j]]
    for (int i = w; i < sr; i += 16) {
        const float* Krow = g_K + (size_t)idr[i] * NB;
        for (int j = lane; j < st; j += 32) S[i * pad + j] = (T)Krow[idt[j]];
    }
    __syncthreads();

    const int i0c = (sr * w) >> 4, i1c = (sr * (w + 1)) >> 4;   // v-update i-chunk
    const int j0c = (st * w) >> 4, j1c = (st * (w + 1)) >> 4;   // u-update j-chunk

    for (int it = 0; it < 20; it++) {
        // v_j = ht_j / (sum_i u_i S[i][j] + eps): i outer, Q j-accumulators
        {
            float acc[8] = {0.f, 0.f, 0.f, 0.f, 0.f, 0.f, 0.f, 0.f};
            for (int i = i0c; i < i1c; i++) {
                float ui = u[i];
                const T* Srow = S + i * pad;
#pragma unroll
                for (int q = 0; q < 8; q++) {
                    int j = lane + 32 * q;
                    if (j < st) acc[q] += ui * (float)Srow[j];
                }
            }
#pragma unroll
            for (int q = 0; q < 8; q++) {
                int j = lane + 32 * q;
                if (j < st) part[w * 256 + j] = acc[q];
            }
        }
        __syncthreads();
        if (tid < st) {
            float d = 0.0f;
#pragma unroll
            for (int ww = 0; ww < 16; ww++) d += part[ww * 256 + tid];
            v[tid] = __fdividef(htw[tid], d + SINK_EPS);
        }
        __syncthreads();
        // u_i = hr_i / (sum_j v_j S[i][j] + eps): j outer, Q i-accumulators
        {
            float acc[8] = {0.f, 0.f, 0.f, 0.f, 0.f, 0.f, 0.f, 0.f};
            for (int j = j0c; j < j1c; j++) {
                float vj = v[j];
#pragma unroll
                for (int q = 0; q < 8; q++) {
                    int i = lane + 32 * q;
                    if (i < sr) acc[q] += vj * (float)S[i * pad + j];
                }
            }
#pragma unroll
            for (int q = 0; q < 8; q++) {
                int i = lane + 32 * q;
                if (i < sr) part[w * 256 + i] = acc[q];
            }
        }
        __syncthreads();
        if (tid < sr) {
            float d = 0.0f;
#pragma unroll
            for (int ww = 0; ww < 16; ww++) d += part[ww * 256 + tid];
            u[tid] = __fdividef(hrw[tid], d + SINK_EPS);
        }
        __syncthreads();
    }

    // re-gather S <- KC, then emd = sum_j v_j * (sum_i u_i KC_ij)
    for (int i = w; i < sr; i += 16) {
        const float* Crow = g_KC + (size_t)idr[i] * NB;
        for (int j = lane; j < st; j += 32) S[i * pad + j] = (T)Crow[idt[j]];
    }
    __syncthreads();
    {
        float acc[8] = {0.f, 0.f, 0.f, 0.f, 0.f, 0.f, 0.f, 0.f};
        for (int i = i0c; i < i1c; i++) {
            float ui = u[i];
            const T* Srow = S + i * pad;
#pragma unroll
            for (int q = 0; q < 8; q++) {
                int j = lane + 32 * q;
                if (j < st) acc[q] += ui * (float)Srow[j];
            }
        }
#pragma unroll
        for (int q = 0; q < 8; q++) {
            int j = lane + 32 * q;
            if (j < st) part[w * 256 + j] = acc[q];
        }
    }
    __syncthreads();
    float e = 0.0f;
    if (tid < st) {
        float d = 0.0f;
#pragma unroll
        for (int ww = 0; ww < 16; ww++) d += part[ww * 256 + tid];
        e = v[tid] * d;
    }
    __syncthreads();
    part[tid] = e;
    __syncthreads();
    for (int o = 256; o > 0; o >>= 1) {
        if (tid < o) part[tid] += part[tid + o];
        __syncthreads();
    }
    if (tid == 0) {
        float r = part[0];
        g_emd[p] = isfinite(r) ? r : 0.0f;
    }
}

__global__ void __launch_bounds__(512) sink_kernel() {
    extern __shared__ float sm[];
    const int p = blockIdx.x;
    const int sr = g_scnt[0][p], st = g_scnt[1][p];
    const int pad = st | 1;                    // odd stride -> conflict-free both axes
    if ((long)sr * pad <= SCAP_F32) sink_body<float>(sm, p, sr, st, pad);
    else                            sink_body<__half>(sm, p, sr, st, pad);
}

// ---------------- half-pixel bilinear upsample 16x16 -> 256x256 ----------------
__global__ void upsample_kernel(float* __restrict__ out) {
    int idx = blockIdx.x * blockDim.x + threadIdx.x;
    if (idx >= 4 * NPIX) return;
    int b = idx >> 16, y = (idx >> 8) & 255, x = idx & 255;
    float fy = (y + 0.5f) * 0.0625f - 0.5f;
    float fx = (x + 0.5f) * 0.0625f - 0.5f;
    int y0 = (int)floorf(fy); float wy = fy - (float)y0;
    int x0 = (int)floorf(fx); float wx = fx - (float)x0;
    int y0c = min(15, max(0, y0)), y1c = min(15, max(0, y0 + 1));
    int x0c = min(15, max(0, x0)), x1c = min(15, max(0, x0 + 1));
    const float* e = g_emd + b * 256;
    float v00 = e[y0c * 16 + x0c], v01 = e[y0c * 16 + x1c];
    float v10 = e[y1c * 16 + x0c], v11 = e[y1c * 16 + x1c];
    v00 = isfinite(v00) ? v00 : 0.0f;
    v01 = isfinite(v01) ? v01 : 0.0f;
    v10 = isfinite(v10) ? v10 : 0.0f;
    v11 = isfinite(v11) ? v11 : 0.0f;
    float t0 = v00 + (v01 - v00) * wx;
    float t1 = v10 + (v11 - v10) * wx;
    out[idx] = t0 + (t1 - t0) * wy;
}

// ---------------- launcher ----------------
extern "C" void kernel_launch(void* const* d_in, const int* in_sizes, int n_in,
                              void* d_out, int out_size) {
    (void)in_sizes; (void)n_in; (void)out_size;
    const float* ref = (const float*)d_in[0];
    const float* tgt = (const float*)d_in[1];
    float* out = (float*)d_out;

    static int smem_set = 0;
    if (!smem_set) {
        cudaFuncSetAttribute(sink_kernel, cudaFuncAttributeMaxDynamicSharedMemorySize,
                             SINK_SMEM_BYTES);
        smem_set = 1;
    }

    init_kernel<<<1, 32>>>();
    oklab_kernel<<<dim3(256, 2), 256>>>(ref, tgt);
    buildK_kernel<<<NB, NB>>>();
    hist_kernel<<<dim3(PCOUNT, 2), 256>>>();
    sink_kernel<<<PCOUNT, 512, SINK_SMEM_BYTES>>>();
    upsample_kernel<<<(4 * NPIX + 255) / 256, 256>>>(out);
}

// round 14
// speedup vs baseline: 1.0301x; 1.0301x over previous
#include <cuda_runtime.h>
#include <cuda_fp16.h>
#include <math.h>
#include <stdint.h>

#define NPIX   65536      // 256*256
#define PCOUNT 1024       // 4 * 16 * 16 patches
#define NB     512        // 8^3 bins
#define SINK_EPS 1e-6f

// sink kernel smem: 230400 bytes dynamic
#define SINK_SMEM_BYTES 230400
#define SINK_SMEM_WORDS (SINK_SMEM_BYTES / 4)   // 57600
#define AUX_WORDS 3584                          // u,v,hrw,htw(1024) + idx(512) + part(2048)
#define SCAP_F32 (SINK_SMEM_WORDS - AUX_WORDS)  // 54016 floats for S

// ---------------- scratch (static device globals; no allocation) ----------------
__device__ float    g_oklab[2][4 * 3 * NPIX];
__device__ unsigned g_mm[12];
__device__ float    g_K[NB * NB];
__device__ float    g_KC[NB * NB];
__device__ int      g_scnt[2][PCOUNT];
__device__ int      g_sidx[2][PCOUNT][256];
__device__ float    g_sw[2][PCOUNT][256];
__device__ float    g_emd[PCOUNT];

// ---------------- helpers ----------------
__device__ __forceinline__ unsigned fenc(float f) {
    unsigned u = __float_as_uint(f);
    return (u & 0x80000000u) ? ~u : (u | 0x80000000u);
}
__device__ __forceinline__ float fdec(unsigned u) {
    return __uint_as_float((u & 0x80000000u) ? (u ^ 0x80000000u) : ~u);
}
__device__ __forceinline__ float srgb_lin(float x) {
    x = fminf(fmaxf(x, 0.0f), 1.0f);
    return (x <= 0.04045f) ? x * (1.0f / 12.92f)
                           : powf((x + 0.055f) * (1.0f / 1.055f), 2.4f);
}
__device__ __forceinline__ void get_lohi(int img, float* lo, float* hi) {
#pragma unroll
    for (int c = 0; c < 3; c++) {
        float l = fdec(g_mm[img * 3 + c]) - 0.01f;
        float h = fdec(g_mm[6 + img * 3 + c]) + 0.01f;
        if (h - l < 1e-4f) { l -= 0.05f; h += 0.05f; }
        lo[c] = l; hi[c] = h;
    }
}

// ---------------- init: minmax sentinels ----------------
__global__ void init_kernel() {
    int idx = threadIdx.x;
    if (idx < 6) g_mm[idx] = 0xFFFFFFFFu;
    else if (idx < 12) g_mm[idx] = 0u;
}

// ---------------- sRGB -> OKLab + per-channel global min/max ----------------
__global__ void oklab_kernel(const float* __restrict__ ref, const float* __restrict__ tgt) {
    const int img = blockIdx.y;
    const float* __restrict__ in = img ? tgt : ref;
    float* __restrict__ outp = g_oklab[img];
    float mn0 = 1e30f, mn1 = 1e30f, mn2 = 1e30f;
    float mx0 = -1e30f, mx1 = -1e30f, mx2 = -1e30f;

    for (int idx = blockIdx.x * blockDim.x + threadIdx.x; idx < 4 * NPIX;
         idx += gridDim.x * blockDim.x) {
        int b = idx >> 16;
        int hw = idx & 65535;
        int base = b * 3 * NPIX + hw;
        float r  = srgb_lin(in[base]);
        float g  = srgb_lin(in[base + NPIX]);
        float bl = srgb_lin(in[base + 2 * NPIX]);
        float l = 0.4122214708f * r + 0.5363325363f * g + 0.0514459929f * bl;
        float m = 0.2119034982f * r + 0.6806995451f * g + 0.1073969566f * bl;
        float s = 0.0883024619f * r + 0.2817188376f * g + 0.6299787005f * bl;
        l = fmaxf(l, 0.0f); m = fmaxf(m, 0.0f); s = fmaxf(s, 0.0f);
        float lg = (l > 0.0f) ? cbrtf(fmaxf(l, 1e-12f)) : 0.0f;
        float mg = (m > 0.0f) ? cbrtf(fmaxf(m, 1e-12f)) : 0.0f;
        float sg = (s > 0.0f) ? cbrtf(fmaxf(s, 1e-12f)) : 0.0f;
        float L = 0.2104542553f * lg + 0.793617785f  * mg - 0.0040720468f * sg;
        float A = 1.9779984951f * lg - 2.428592205f  * mg + 0.4505937099f * sg;
        float B = 0.0259040371f * lg + 0.7827717662f * mg - 0.808675766f  * sg;
        outp[base] = L; outp[base + NPIX] = A; outp[base + 2 * NPIX] = B;
        mn0 = fminf(mn0, L); mx0 = fmaxf(mx0, L);
        mn1 = fminf(mn1, A); mx1 = fmaxf(mx1, A);
        mn2 = fminf(mn2, B); mx2 = fmaxf(mx2, B);
    }
#pragma unroll
    for (int o = 16; o > 0; o >>= 1) {
        mn0 = fminf(mn0, __shfl_down_sync(0xffffffffu, mn0, o));
        mn1 = fminf(mn1, __shfl_down_sync(0xffffffffu, mn1, o));
        mn2 = fminf(mn2, __shfl_down_sync(0xffffffffu, mn2, o));
        mx0 = fmaxf(mx0, __shfl_down_sync(0xffffffffu, mx0, o));
        mx1 = fmaxf(mx1, __shfl_down_sync(0xffffffffu, mx1, o));
        mx2 = fmaxf(mx2, __shfl_down_sync(0xffffffffu, mx2, o));
    }
    if ((threadIdx.x & 31) == 0) {
        atomicMin(&g_mm[img * 3 + 0], fenc(mn0));
        atomicMin(&g_mm[img * 3 + 1], fenc(mn1));
        atomicMin(&g_mm[img * 3 + 2], fenc(mn2));
        atomicMax(&g_mm[6 + img * 3 + 0], fenc(mx0));
        atomicMax(&g_mm[6 + img * 3 + 1], fenc(mx1));
        atomicMax(&g_mm[6 + img * 3 + 2], fenc(mx2));
    }
}

// ---------------- build K = exp(-cost/REG) and KC = K*cost on averaged grid ----------------
__global__ void buildK_kernel() {
    int i = blockIdx.x, j = threadIdx.x;
    float lor[3], hir[3], lot[3], hit[3];
    get_lohi(0, lor, hir);
    get_lohi(1, lot, hit);
    float step[3];
#pragma unroll
    for (int c = 0; c < 3; c++)
        step[c] = ((hir[c] - lor[c]) + (hit[c] - lot[c])) * 0.5f * 0.125f;
    int i0 = i >> 6, i1 = (i >> 3) & 7, i2 = i & 7;
    int j0 = j >> 6, j1 = (j >> 3) & 7, j2 = j & 7;
    float d0 = step[0] * (float)(i0 - j0);
    float d1 = step[1] * (float)(i1 - j1);
    float d2 = step[2] * (float)(i2 - j2);
    float dd = d0 * d0 + d1 * d1 + d2 * d2;
    float cost = (dd > 0.0f) ? sqrtf(dd) : 0.0f;
    float Kv = expf(-cost * 10.0f);        // REG = 0.1
    g_K[i * NB + j]  = Kv;
    g_KC[i * NB + j] = Kv * cost;
}

// ---------------- per-patch histograms + deterministic support-list extraction --------
__global__ void hist_kernel() {
    const int img = blockIdx.y, p = blockIdx.x, t = threadIdx.x;   // 256 threads
    __shared__ float h[NB];
    __shared__ int sca[NB], scb[NB];
    __shared__ float lo_s[3], inv_s[3];
    if (t == 0) {
        float lo[3], hi[3];
        get_lohi(img, lo, hi);
#pragma unroll
        for (int c = 0; c < 3; c++) { lo_s[c] = lo[c]; inv_s[c] = 8.0f / (hi[c] - lo[c]); }
    }
    h[t] = 0.0f; h[t + 256] = 0.0f;
    __syncthreads();

    int b = p >> 8, ph = (p >> 4) & 15, pw = p & 15;
    int py = t >> 4, px = t & 15;
    int hh = (ph << 4) + py, ww = (pw << 4) + px;
    int base = b * 3 * NPIX + hh * 256 + ww;
    const float* ok = g_oklab[img];
    float xL = ok[base], xA = ok[base + NPIX], xB = ok[base + 2 * NPIX];
    int i0 = (int)floorf((xL - lo_s[0]) * inv_s[0]); i0 = min(7, max(0, i0));
    int i1 = (int)floorf((xA - lo_s[1]) * inv_s[1]); i1 = min(7, max(0, i1));
    int i2 = (int)floorf((xB - lo_s[2]) * inv_s[2]); i2 = min(7, max(0, i2));
    atomicAdd(&h[(i0 << 6) | (i1 << 3) | i2], 1.0f);
    __syncthreads();

    // inclusive prefix scan of occupancy flags over 512 bins (Hillis-Steele, ping-pong)
    sca[t] = (h[t] > 0.0f) ? 1 : 0;
    sca[t + 256] = (h[t + 256] > 0.0f) ? 1 : 0;
    __syncthreads();
    int* src = sca; int* dst = scb;
    for (int off = 1; off < NB; off <<= 1) {
#pragma unroll
        for (int q = 0; q < 2; q++) {
            int i = t + q * 256;
            dst[i] = src[i] + ((i >= off) ? src[i - off] : 0);
        }
        __syncthreads();
        int* tmp = src; src = dst; dst = tmp;
    }

#pragma unroll
    for (int q = 0; q < 2; q++) {
        int i = t + q * 256;
        if (h[i] > 0.0f) {
            int pos = src[i] - 1;
            g_sidx[img][p][pos] = i;
            g_sw[img][p][pos]   = h[i] * (1.0f / 256.0f);
        }
    }
    if (t == 0) g_scnt[img][p] = src[NB - 1];
}

// ---------------- per-patch Sinkhorn: all 20 iterations CTA-local over sparse support --
// smem word layout: u[256] v[256] hrw[256] htw[256] idr[256] idt[256] part[8*256] S[...]
template <typename T>
__device__ void sink_body(float* sm, int p, int sr, int st, int pad) {
    float* u   = sm;
    float* v   = sm + 256;
    float* hrw = sm + 512;
    float* htw = sm + 768;
    int*   idr = (int*)(sm + 1024);
    int*   idt = (int*)(sm + 1280);
    float* part = sm + 1536;              // [8][256]
    T*     S   = (T*)(sm + AUX_WORDS);

    const int tid = threadIdx.x, lane = tid & 31, w = tid >> 5;   // 8 warps

    if (tid < sr) { idr[tid] = g_sidx[0][p][tid]; hrw[tid] = g_sw[0][p][tid]; u[tid] = 1.0f; }
    if (tid < st) { idt[tid] = g_sidx[1][p][tid]; htw[tid] = g_sw[1][p][tid]; }
    __syncthreads();

    // gather S[i][j] = K[idr[i], idt[j]]
    for (int i = w; i < sr; i += 8) {
        const float* Krow = g_K + (size_t)idr[i] * NB;
        for (int j = lane; j < st; j += 32) S[i * pad + j] = (T)Krow[idt[j]];
    }
    __syncthreads();

    const int i0c = (sr * w) >> 3, i1c = (sr * (w + 1)) >> 3;   // v-update row chunk
    const int j0c = (st * w) >> 3, j1c = (st * (w + 1)) >> 3;   // u-update col chunk
    float* pw = part + w * 256;

    for (int it = 0; it < 20; it++) {
        // v_j = ht_j / (sum_i u_i S[i][j] + eps): i outer, 8 register col-accumulators
        {
            float acc[8] = {0.f, 0.f, 0.f, 0.f, 0.f, 0.f, 0.f, 0.f};
            for (int i = i0c; i < i1c; i++) {
                float ui = u[i];                       // warp-uniform broadcast
                const T* Srow = S + i * pad;
#pragma unroll
                for (int q = 0; q < 8; q++) {
                    int j = lane + 32 * q;
                    if (j < st) acc[q] += ui * (float)Srow[j];
                }
            }
#pragma unroll
            for (int q = 0; q < 8; q++) {
                int j = lane + 32 * q;
                if (j < st) pw[j] = acc[q];
            }
        }
        __syncthreads();
        if (tid < st) {
            float d = part[tid] + part[256 + tid] + part[512 + tid] + part[768 + tid]
                    + part[1024 + tid] + part[1280 + tid] + part[1536 + tid] + part[1792 + tid];
            v[tid] = __fdividef(htw[tid], d + SINK_EPS);
        }
        __syncthreads();
        // u_i = hr_i / (sum_j v_j S[i][j] + eps): j outer, 8 register row-accumulators
        {
            float acc[8] = {0.f, 0.f, 0.f, 0.f, 0.f, 0.f, 0.f, 0.f};
            for (int j = j0c; j < j1c; j++) {
                float vj = v[j];                       // warp-uniform broadcast
#pragma unroll
                for (int q = 0; q < 8; q++) {
                    int i = lane + 32 * q;
                    if (i < sr) acc[q] += vj * (float)S[i * pad + j];
                }
            }
#pragma unroll
            for (int q = 0; q < 8; q++) {
                int i = lane + 32 * q;
                if (i < sr) pw[i] = acc[q];
            }
        }
        __syncthreads();
        if (tid < sr) {
            float d = part[tid] + part[256 + tid] + part[512 + tid] + part[768 + tid]
                    + part[1024 + tid] + part[1280 + tid] + part[1536 + tid] + part[1792 + tid];
            u[tid] = __fdividef(hrw[tid], d + SINK_EPS);
        }
        __syncthreads();
    }

    // re-gather S <- KC, then emd = sum_j v_j * (sum_i u_i KC_ij)
    for (int i = w; i < sr; i += 8) {
        const float* Crow = g_KC + (size_t)idr[i] * NB;
        for (int j = lane; j < st; j += 32) S[i * pad + j] = (T)Crow[idt[j]];
    }
    __syncthreads();
    {
        float acc[8] = {0.f, 0.f, 0.f, 0.f, 0.f, 0.f, 0.f, 0.f};
        for (int i = i0c; i < i1c; i++) {
            float ui = u[i];
            const T* Srow = S + i * pad;
#pragma unroll
            for (int q = 0; q < 8; q++) {
                int j = lane + 32 * q;
                if (j < st) acc[q] += ui * (float)Srow[j];
            }
        }
#pragma unroll
        for (int q = 0; q < 8; q++) {
            int j = lane + 32 * q;
            if (j < st) pw[j] = acc[q];
        }
    }
    __syncthreads();
    float e = 0.0f;
    if (tid < st) {
        float d = part[tid] + part[256 + tid] + part[512 + tid] + part[768 + tid]
                + part[1024 + tid] + part[1280 + tid] + part[1536 + tid] + part[1792 + tid];
        e = v[tid] * d;
    }
    __syncthreads();
    part[tid] = e;
    __syncthreads();
    for (int o = 128; o > 0; o >>= 1) {
        if (tid < o) part[tid] += part[tid + o];
        __syncthreads();
    }
    if (tid == 0) {
        float r = part[0];
        g_emd[p] = isfinite(r) ? r : 0.0f;
    }
}

__global__ void __launch_bounds__(256) sink_kernel() {
    extern __shared__ float sm[];
    const int p = blockIdx.x;
    const int sr = g_scnt[0][p], st = g_scnt[1][p];
    const int pad = st | 1;                    // odd stride -> conflict-free both axes
    if ((long)sr * pad <= SCAP_F32) sink_body<float>(sm, p, sr, st, pad);
    else                            sink_body<__half>(sm, p, sr, st, pad);
}

// ---------------- half-pixel bilinear upsample 16x16 -> 256x256 ----------------
__global__ void upsample_kernel(float* __restrict__ out) {
    int idx = blockIdx.x * blockDim.x + threadIdx.x;
    if (idx >= 4 * NPIX) return;
    int b = idx >> 16, y = (idx >> 8) & 255, x = idx & 255;
    float fy = (y + 0.5f) * 0.0625f - 0.5f;
    float fx = (x + 0.5f) * 0.0625f - 0.5f;
    int y0 = (int)floorf(fy); float wy = fy - (float)y0;
    int x0 = (int)floorf(fx); float wx = fx - (float)x0;
    int y0c = min(15, max(0, y0)), y1c = min(15, max(0, y0 + 1));
    int x0c = min(15, max(0, x0)), x1c = min(15, max(0, x0 + 1));
    const float* e = g_emd + b * 256;
    float v00 = e[y0c * 16 + x0c], v01 = e[y0c * 16 + x1c];
    float v10 = e[y1c * 16 + x0c], v11 = e[y1c * 16 + x1c];
    v00 = isfinite(v00) ? v00 : 0.0f;
    v01 = isfinite(v01) ? v01 : 0.0f;
    v10 = isfinite(v10) ? v10 : 0.0f;
    v11 = isfinite(v11) ? v11 : 0.0f;
    float t0 = v00 + (v01 - v00) * wx;
    float t1 = v10 + (v11 - v10) * wx;
    out[idx] = t0 + (t1 - t0) * wy;
}

// ---------------- launcher ----------------
extern "C" void kernel_launch(void* const* d_in, const int* in_sizes, int n_in,
                              void* d_out, int out_size) {
    (void)in_sizes; (void)n_in; (void)out_size;
    const float* ref = (const float*)d_in[0];
    const float* tgt = (const float*)d_in[1];
    float* out = (float*)d_out;

    static int smem_set = 0;
    if (!smem_set) {
        cudaFuncSetAttribute(sink_kernel, cudaFuncAttributeMaxDynamicSharedMemorySize,
                             SINK_SMEM_BYTES);
        smem_set = 1;
    }

    init_kernel<<<1, 32>>>();
    oklab_kernel<<<dim3(256, 2), 256>>>(ref, tgt);
    buildK_kernel<<<NB, NB>>>();
    hist_kernel<<<dim3(PCOUNT, 2), 256>>>();
    sink_kernel<<<PCOUNT, 256, SINK_SMEM_BYTES>>>();
    upsample_kernel<<<(4 * NPIX + 255) / 256, 256>>>(out);
}

// round 16
// speedup vs baseline: 1.1930x; 1.1581x over previous
#include <cuda_runtime.h>
#include <cuda_fp16.h>
#include <math.h>
#include <stdint.h>

#define NPIX   65536      // 256*256
#define PCOUNT 1024       // 4 * 16 * 16 patches
#define NB     512        // 8^3 bins
#define SINK_EPS 1e-6f

// ---- fast path (half S, 2 CTAs/SM) ----
#define SMEM_A_BYTES 112640                     // 110KB -> 2 CTAs/SM
#define SMEM_A_WORDS (SMEM_A_BYTES / 4)         // 28160
#define AUX_A_WORDS  3712                       // u,v,hrw,htw,idr,idt(1536) + vh(128) + part(2048)
#define SCAP_HALF ((SMEM_A_WORDS - AUX_A_WORDS) * 2)   // 48896 halves for S

// ---- fallback path (fp32 S, 1 CTA/SM) = R11 ----
#define SINK_SMEM_BYTES 230400
#define SINK_SMEM_WORDS (SINK_SMEM_BYTES / 4)
#define AUX_WORDS 3584
#define SCAP_F32 (SINK_SMEM_WORDS - AUX_WORDS)  // 54016 floats for S

// ---------------- scratch (static device globals; no allocation) ----------------
__device__ float    g_oklab[2][4 * 3 * NPIX];
__device__ unsigned g_mm[12];
__device__ float    g_K[NB * NB];
__device__ float    g_KC[NB * NB];
__device__ int      g_scnt[2][PCOUNT];
__device__ int      g_sidx[2][PCOUNT][256];
__device__ float    g_sw[2][PCOUNT][256];
__device__ float    g_emd[PCOUNT];

// ---------------- helpers ----------------
__device__ __forceinline__ unsigned fenc(float f) {
    unsigned u = __float_as_uint(f);
    return (u & 0x80000000u) ? ~u : (u | 0x80000000u);
}
__device__ __forceinline__ float fdec(unsigned u) {
    return __uint_as_float((u & 0x80000000u) ? (u ^ 0x80000000u) : ~u);
}
__device__ __forceinline__ float srgb_lin(float x) {
    x = fminf(fmaxf(x, 0.0f), 1.0f);
    return (x <= 0.04045f) ? x * (1.0f / 12.92f)
                           : powf((x + 0.055f) * (1.0f / 1.055f), 2.4f);
}
__device__ __forceinline__ void get_lohi(int img, float* lo, float* hi) {
#pragma unroll
    for (int c = 0; c < 3; c++) {
        float l = fdec(g_mm[img * 3 + c]) - 0.01f;
        float h = fdec(g_mm[6 + img * 3 + c]) + 0.01f;
        if (h - l < 1e-4f) { l -= 0.05f; h += 0.05f; }
        lo[c] = l; hi[c] = h;
    }
}

// ---------------- init: minmax sentinels ----------------
__global__ void init_kernel() {
    int idx = threadIdx.x;
    if (idx < 6) g_mm[idx] = 0xFFFFFFFFu;
    else if (idx < 12) g_mm[idx] = 0u;
}

// ---------------- sRGB -> OKLab + per-channel global min/max ----------------
__global__ void oklab_kernel(const float* __restrict__ ref, const float* __restrict__ tgt) {
    const int img = blockIdx.y;
    const float* __restrict__ in = img ? tgt : ref;
    float* __restrict__ outp = g_oklab[img];
    float mn0 = 1e30f, mn1 = 1e30f, mn2 = 1e30f;
    float mx0 = -1e30f, mx1 = -1e30f, mx2 = -1e30f;

    for (int idx = blockIdx.x * blockDim.x + threadIdx.x; idx < 4 * NPIX;
         idx += gridDim.x * blockDim.x) {
        int b = idx >> 16;
        int hw = idx & 65535;
        int base = b * 3 * NPIX + hw;
        float r  = srgb_lin(in[base]);
        float g  = srgb_lin(in[base + NPIX]);
        float bl = srgb_lin(in[base + 2 * NPIX]);
        float l = 0.4122214708f * r + 0.5363325363f * g + 0.0514459929f * bl;
        float m = 0.2119034982f * r + 0.6806995451f * g + 0.1073969566f * bl;
        float s = 0.0883024619f * r + 0.2817188376f * g + 0.6299787005f * bl;
        l = fmaxf(l, 0.0f); m = fmaxf(m, 0.0f); s = fmaxf(s, 0.0f);
        float lg = (l > 0.0f) ? cbrtf(fmaxf(l, 1e-12f)) : 0.0f;
        float mg = (m > 0.0f) ? cbrtf(fmaxf(m, 1e-12f)) : 0.0f;
        float sg = (s > 0.0f) ? cbrtf(fmaxf(s, 1e-12f)) : 0.0f;
        float L = 0.2104542553f * lg + 0.793617785f  * mg - 0.0040720468f * sg;
        float A = 1.9779984951f * lg - 2.428592205f  * mg + 0.4505937099f * sg;
        float B = 0.0259040371f * lg + 0.7827717662f * mg - 0.808675766f  * sg;
        outp[base] = L; outp[base + NPIX] = A; outp[base + 2 * NPIX] = B;
        mn0 = fminf(mn0, L); mx0 = fmaxf(mx0, L);
        mn1 = fminf(mn1, A); mx1 = fmaxf(mx1, A);
        mn2 = fminf(mn2, B); mx2 = fmaxf(mx2, B);
    }
#pragma unroll
    for (int o = 16; o > 0; o >>= 1) {
        mn0 = fminf(mn0, __shfl_down_sync(0xffffffffu, mn0, o));
        mn1 = fminf(mn1, __shfl_down_sync(0xffffffffu, mn1, o));
        mn2 = fminf(mn2, __shfl_down_sync(0xffffffffu, mn2, o));
        mx0 = fmaxf(mx0, __shfl_down_sync(0xffffffffu, mx0, o));
        mx1 = fmaxf(mx1, __shfl_down_sync(0xffffffffu, mx1, o));
        mx2 = fmaxf(mx2, __shfl_down_sync(0xffffffffu, mx2, o));
    }
    if ((threadIdx.x & 31) == 0) {
        atomicMin(&g_mm[img * 3 + 0], fenc(mn0));
        atomicMin(&g_mm[img * 3 + 1], fenc(mn1));
        atomicMin(&g_mm[img * 3 + 2], fenc(mn2));
        atomicMax(&g_mm[6 + img * 3 + 0], fenc(mx0));
        atomicMax(&g_mm[6 + img * 3 + 1], fenc(mx1));
        atomicMax(&g_mm[6 + img * 3 + 2], fenc(mx2));
    }
}

// ---------------- build K = exp(-cost/REG) and KC = K*cost on averaged grid ----------------
__global__ void buildK_kernel() {
    int i = blockIdx.x, j = threadIdx.x;
    float lor[3], hir[3], lot[3], hit[3];
    get_lohi(0, lor, hir);
    get_lohi(1, lot, hit);
    float step[3];
#pragma unroll
    for (int c = 0; c < 3; c++)
        step[c] = ((hir[c] - lor[c]) + (hit[c] - lot[c])) * 0.5f * 0.125f;
    int i0 = i >> 6, i1 = (i >> 3) & 7, i2 = i & 7;
    int j0 = j >> 6, j1 = (j >> 3) & 7, j2 = j & 7;
    float d0 = step[0] * (float)(i0 - j0);
    float d1 = step[1] * (float)(i1 - j1);
    float d2 = step[2] * (float)(i2 - j2);
    float dd = d0 * d0 + d1 * d1 + d2 * d2;
    float cost = (dd > 0.0f) ? sqrtf(dd) : 0.0f;
    float Kv = expf(-cost * 10.0f);        // REG = 0.1
    g_K[i * NB + j]  = Kv;
    g_KC[i * NB + j] = Kv * cost;
}

// ---------------- per-patch histograms + deterministic support-list extraction --------
__global__ void hist_kernel() {
    const int img = blockIdx.y, p = blockIdx.x, t = threadIdx.x;   // 256 threads
    __shared__ float h[NB];
    __shared__ int sca[NB], scb[NB];
    __shared__ float lo_s[3], inv_s[3];
    if (t == 0) {
        float lo[3], hi[3];
        get_lohi(img, lo, hi);
#pragma unroll
        for (int c = 0; c < 3; c++) { lo_s[c] = lo[c]; inv_s[c] = 8.0f / (hi[c] - lo[c]); }
    }
    h[t] = 0.0f; h[t + 256] = 0.0f;
    __syncthreads();

    int b = p >> 8, ph = (p >> 4) & 15, pw = p & 15;
    int py = t >> 4, px = t & 15;
    int hh = (ph << 4) + py, ww = (pw << 4) + px;
    int base = b * 3 * NPIX + hh * 256 + ww;
    const float* ok = g_oklab[img];
    float xL = ok[base], xA = ok[base + NPIX], xB = ok[base + 2 * NPIX];
    int i0 = (int)floorf((xL - lo_s[0]) * inv_s[0]); i0 = min(7, max(0, i0));
    int i1 = (int)floorf((xA - lo_s[1]) * inv_s[1]); i1 = min(7, max(0, i1));
    int i2 = (int)floorf((xB - lo_s[2]) * inv_s[2]); i2 = min(7, max(0, i2));
    atomicAdd(&h[(i0 << 6) | (i1 << 3) | i2], 1.0f);
    __syncthreads();

    // inclusive prefix scan of occupancy flags over 512 bins (Hillis-Steele, ping-pong)
    sca[t] = (h[t] > 0.0f) ? 1 : 0;
    sca[t + 256] = (h[t + 256] > 0.0f) ? 1 : 0;
    __syncthreads();
    int* src = sca; int* dst = scb;
    for (int off = 1; off < NB; off <<= 1) {
#pragma unroll
        for (int q = 0; q < 2; q++) {
            int i = t + q * 256;
            dst[i] = src[i] + ((i >= off) ? src[i - off] : 0);
        }
        __syncthreads();
        int* tmp = src; src = dst; dst = tmp;
    }

#pragma unroll
    for (int q = 0; q < 2; q++) {
        int i = t + q * 256;
        if (h[i] > 0.0f) {
            int pos = src[i] - 1;
            g_sidx[img][p][pos] = i;
            g_sw[img][p][pos]   = h[i] * (1.0f / 256.0f);
        }
    }
    if (t == 0) g_scnt[img][p] = src[NB - 1];
}

// =============== FAST sinkhorn: half S, half2 row-major both updates, 2 CTAs/SM =======
// smem words: u[256] v[256] hrw[256] htw[256] idr[256] idt[256] vh[128w=256h] part[8*256] S
__global__ void __launch_bounds__(256) sink_a() {
    extern __shared__ float sm[];
    const int p = blockIdx.x;
    const int sr = g_scnt[0][p], st = g_scnt[1][p];
    const int pad2 = (st + 1) & ~1;                 // even; element st zero-filled if st odd
    if ((long)sr * pad2 > SCAP_HALF) return;        // fallback pass handles

    float*  u   = sm;
    float*  v   = sm + 256;
    float*  hrw = sm + 512;
    float*  htw = sm + 768;
    int*    idr = (int*)(sm + 1024);
    int*    idt = (int*)(sm + 1280);
    __half* vh  = (__half*)(sm + 1536);             // 256 halves
    float*  part = sm + 1664;                       // [8][256]
    __half* S   = (__half*)(sm + AUX_A_WORDS);

    const int tid = threadIdx.x, lane = tid & 31, w = tid >> 5;   // 8 warps
    const int ngrp = (st + 63) >> 6;                // half2 column groups of 64

    if (tid < sr) { idr[tid] = g_sidx[0][p][tid]; hrw[tid] = g_sw[0][p][tid]; u[tid] = 1.0f; }
    if (tid < st) { idt[tid] = g_sidx[1][p][tid]; htw[tid] = g_sw[1][p][tid]; }
    vh[tid] = __float2half(0.0f);                   // pre-zero (pad element stays 0)
    __syncthreads();

    // gather S[i][j] = half(K[idr[i], idt[j]]), zero-fill pad column
    for (int i = w; i < sr; i += 8) {
        const float* Krow = g_K + (size_t)idr[i] * NB;
        for (int j = lane; j < pad2; j += 32)
            S[i * pad2 + j] = __float2half((j < st) ? Krow[idt[j]] : 0.0f);
    }
    __syncthreads();

    const int i0c = (sr * w) >> 3, i1c = (sr * (w + 1)) >> 3;   // v-update row chunk
    float* pw = part + w * 256;

    for (int it = 0; it < 20; it++) {
        // ---- v_j = ht_j / (sum_i u_i S[i][j] + eps): u-broadcast, half2 rows ----
        {
            float2 acc[4] = {{0.f,0.f},{0.f,0.f},{0.f,0.f},{0.f,0.f}};
            for (int i = i0c; i < i1c; i++) {
                float ui = u[i];                          // warp-uniform broadcast
                const __half2* Srow = (const __half2*)(S + i * pad2);
#pragma unroll
                for (int g = 0; g < 4; g++) {
                    int j0 = g * 64 + 2 * lane;
                    if (g < ngrp && j0 < st) {
                        float2 s2 = __half22float2(Srow[g * 32 + lane]);
                        acc[g].x += ui * s2.x;
                        acc[g].y += ui * s2.y;
                    }
                }
            }
#pragma unroll
            for (int g = 0; g < 4; g++) {
                int j0 = g * 64 + 2 * lane;
                if (g < ngrp && j0 < st) *(float2*)(pw + j0) = acc[g];
            }
        }
        __syncthreads();
        if (tid < st) {
            float d = part[tid] + part[256 + tid] + part[512 + tid] + part[768 + tid]
                    + part[1024 + tid] + part[1280 + tid] + part[1536 + tid] + part[1792 + tid];
            float val = __fdividef(htw[tid], d + SINK_EPS);
            v[tid] = val;
            vh[tid] = __float2half(val);
        }
        __syncthreads();
        // ---- u_i = hr_i / (sum_j v_j S[i][j] + eps): warp-per-row dot, half2 ----
        for (int i = w; i < sr; i += 8) {
            const __half2* Srow = (const __half2*)(S + i * pad2);
            const __half2* vh2  = (const __half2*)vh;
            float acc = 0.0f;
#pragma unroll
            for (int g = 0; g < 4; g++) {
                int j0 = g * 64 + 2 * lane;
                if (g < ngrp && j0 < st) {
                    float2 s2 = __half22float2(Srow[g * 32 + lane]);
                    float2 vv = __half22float2(vh2[g * 32 + lane]);
                    acc += s2.x * vv.x + s2.y * vv.y;
                }
            }
#pragma unroll
            for (int o = 16; o > 0; o >>= 1)
                acc += __shfl_xor_sync(0xffffffffu, acc, o);
            if (lane == 0) u[i] = __fdividef(hrw[i], acc + SINK_EPS);
        }
        __syncthreads();
    }

    // ---- re-gather S <- KC; emd = sum_j v_j * (sum_i u_i KC_ij) (v fp32, u fp32) ----
    for (int i = w; i < sr; i += 8) {
        const float* Crow = g_KC + (size_t)idr[i] * NB;
        for (int j = lane; j < pad2; j += 32)
            S[i * pad2 + j] = __float2half((j < st) ? Crow[idt[j]] : 0.0f);
    }
    __syncthreads();
    {
        float2 acc[4] = {{0.f,0.f},{0.f,0.f},{0.f,0.f},{0.f,0.f}};
        for (int i = i0c; i < i1c; i++) {
            float ui = u[i];
            const __half2* Srow = (const __half2*)(S + i * pad2);
#pragma unroll
            for (int g = 0; g < 4; g++) {
                int j0 = g * 64 + 2 * lane;
                if (g < ngrp && j0 < st) {
                    float2 s2 = __half22float2(Srow[g * 32 + lane]);
                    acc[g].x += ui * s2.x;
                    acc[g].y += ui * s2.y;
                }
            }
        }
#pragma unroll
        for (int g = 0; g < 4; g++) {
            int j0 = g * 64 + 2 * lane;
            if (g < ngrp && j0 < st) *(float2*)(pw + j0) = acc[g];
        }
    }
    __syncthreads();
    float e = 0.0f;
    if (tid < st) {
        float d = part[tid] + part[256 + tid] + part[512 + tid] + part[768 + tid]
                + part[1024 + tid] + part[1280 + tid] + part[1536 + tid] + part[1792 + tid];
        e = v[tid] * d;
    }
    __syncthreads();
    part[tid] = e;
    __syncthreads();
    for (int o = 128; o > 0; o >>= 1) {
        if (tid < o) part[tid] += part[tid + o];
        __syncthreads();
    }
    if (tid == 0) {
        float r = part[0];
        g_emd[p] = isfinite(r) ? r : 0.0f;
    }
}

// =============== FALLBACK sinkhorn (R11 fp32 path) for oversized supports =============
template <typename T>
__device__ void sink_body(float* sm, int p, int sr, int st, int pad) {
    float* u   = sm;
    float* v   = sm + 256;
    float* hrw = sm + 512;
    float* htw = sm + 768;
    int*   idr = (int*)(sm + 1024);
    int*   idt = (int*)(sm + 1280);
    float* part = sm + 1536;              // [8][256]
    T*     S   = (T*)(sm + AUX_WORDS);

    const int tid = threadIdx.x, lane = tid & 31, w = tid >> 5;

    if (tid < sr) { idr[tid] = g_sidx[0][p][tid]; hrw[tid] = g_sw[0][p][tid]; u[tid] = 1.0f; }
    if (tid < st) { idt[tid] = g_sidx[1][p][tid]; htw[tid] = g_sw[1][p][tid]; }
    __syncthreads();

    for (int i = w; i < sr; i += 8) {
        const float* Krow = g_K + (size_t)idr[i] * NB;
        for (int j = lane; j < st; j += 32) S[i * pad + j] = (T)Krow[idt[j]];
    }
    __syncthreads();

    const int iw0 = (sr * w) >> 3, iw1 = (sr * (w + 1)) >> 3;
    const int jw0 = (st * w) >> 3, jw1 = (st * (w + 1)) >> 3;

    for (int it = 0; it < 20; it++) {
        for (int j = lane; j < st; j += 32) {
            float acc = 0.0f;
            for (int i = iw0; i < iw1; i++) acc += u[i] * (float)S[i * pad + j];
            part[w * 256 + j] = acc;
        }
        __syncthreads();
        if (tid < st) {
            float d = part[tid] + part[256 + tid] + part[512 + tid] + part[768 + tid]
                    + part[1024 + tid] + part[1280 + tid] + part[1536 + tid] + part[1792 + tid];
            v[tid] = __fdividef(htw[tid], d + SINK_EPS);
        }
        __syncthreads();
        for (int i = lane; i < sr; i += 32) {
            float acc = 0.0f;
            for (int j = jw0; j < jw1; j++) acc += v[j] * (float)S[i * pad + j];
            part[w * 256 + i] = acc;
        }
        __syncthreads();
        if (tid < sr) {
            float d = part[tid] + part[256 + tid] + part[512 + tid] + part[768 + tid]
                    + part[1024 + tid] + part[1280 + tid] + part[1536 + tid] + part[1792 + tid];
            u[tid] = __fdividef(hrw[tid], d + SINK_EPS);
        }
        __syncthreads();
    }

    for (int i = w; i < sr; i += 8) {
        const float* Crow = g_KC + (size_t)idr[i] * NB;
        for (int j = lane; j < st; j += 32) S[i * pad + j] = (T)Crow[idt[j]];
    }
    __syncthreads();
    for (int j = lane; j < st; j += 32) {
        float acc = 0.0f;
        for (int i = iw0; i < iw1; i++) acc += u[i] * (float)S[i * pad + j];
        part[w * 256 + j] = acc;
    }
    __syncthreads();
    float e = 0.0f;
    if (tid < st) {
        float d = part[tid] + part[256 + tid] + part[512 + tid] + part[768 + tid]
                + part[1024 + tid] + part[1280 + tid] + part[1536 + tid] + part[1792 + tid];
        e = v[tid] * d;
    }
    __syncthreads();
    part[tid] = e;
    __syncthreads();
    for (int o = 128; o > 0; o >>= 1) {
        if (tid < o) part[tid] += part[tid + o];
        __syncthreads();
    }
    if (tid == 0) {
        float r = part[0];
        g_emd[p] = isfinite(r) ? r : 0.0f;
    }
}

__global__ void __launch_bounds__(256) sink_b() {
    extern __shared__ float sm[];
    const int p = blockIdx.x;
    const int sr = g_scnt[0][p], st = g_scnt[1][p];
    const int pad2 = (st + 1) & ~1;
    if ((long)sr * pad2 <= SCAP_HALF) return;       // already done by sink_a
    const int pad = st | 1;
    if ((long)sr * pad <= SCAP_F32) sink_body<float>(sm, p, sr, st, pad);
    else                            sink_body<__half>(sm, p, sr, st, pad);
}

// ---------------- half-pixel bilinear upsample 16x16 -> 256x256 ----------------
__global__ void upsample_kernel(float* __restrict__ out) {
    int idx = blockIdx.x * blockDim.x + threadIdx.x;
    if (idx >= 4 * NPIX) return;
    int b = idx >> 16, y = (idx >> 8) & 255, x = idx & 255;
    float fy = (y + 0.5f) * 0.0625f - 0.5f;
    float fx = (x + 0.5f) * 0.0625f - 0.5f;
    int y0 = (int)floorf(fy); float wy = fy - (float)y0;
    int x0 = (int)floorf(fx); float wx = fx - (float)x0;
    int y0c = min(15, max(0, y0)), y1c = min(15, max(0, y0 + 1));
    int x0c = min(15, max(0, x0)), x1c = min(15, max(0, x0 + 1));
    const float* e = g_emd + b * 256;
    float v00 = e[y0c * 16 + x0c], v01 = e[y0c * 16 + x1c];
    float v10 = e[y1c * 16 + x0c], v11 = e[y1c * 16 + x1c];
    v00 = isfinite(v00) ? v00 : 0.0f;
    v01 = isfinite(v01) ? v01 : 0.0f;
    v10 = isfinite(v10) ? v10 : 0.0f;
    v11 = isfinite(v11) ? v11 : 0.0f;
    float t0 = v00 + (v01 - v00) * wx;
    float t1 = v10 + (v11 - v10) * wx;
    out[idx] = t0 + (t1 - t0) * wy;
}

// ---------------- launcher ----------------
extern "C" void kernel_launch(void* const* d_in, const int* in_sizes, int n_in,
                              void* d_out, int out_size) {
    (void)in_sizes; (void)n_in; (void)out_size;
    const float* ref = (const float*)d_in[0];
    const float* tgt = (const float*)d_in[1];
    float* out = (float*)d_out;

    static int smem_set = 0;
    if (!smem_set) {
        cudaFuncSetAttribute(sink_a, cudaFuncAttributeMaxDynamicSharedMemorySize,
                             SMEM_A_BYTES);
        cudaFuncSetAttribute(sink_b, cudaFuncAttributeMaxDynamicSharedMemorySize,
                             SINK_SMEM_BYTES);
        smem_set = 1;
    }

    init_kernel<<<1, 32>>>();
    oklab_kernel<<<dim3(256, 2), 256>>>(ref, tgt);
    buildK_kernel<<<NB, NB>>>();
    hist_kernel<<<dim3(PCOUNT, 2), 256>>>();
    sink_a<<<PCOUNT, 256, SMEM_A_BYTES>>>();
    sink_b<<<PCOUNT, 256, SINK_SMEM_BYTES>>>();
    upsample_kernel<<<(4 * NPIX + 255) / 256, 256>>>(out);
}

// round 17
// speedup vs baseline: 1.3413x; 1.1243x over previous
#include <cuda_runtime.h>
#include <cuda_fp16.h>
#include <math.h>
#include <stdint.h>

#define NPIX   65536      // 256*256
#define PCOUNT 1024       // 4 * 16 * 16 patches
#define NB     512        // 8^3 bins
#define SINK_EPS 1e-6f

// ---- fast path (half S, 2 CTAs/SM) ----
#define SMEM_A_BYTES 112640                     // 110KB -> 2 CTAs/SM
#define SMEM_A_WORDS (SMEM_A_BYTES / 4)         // 28160
#define AUX_A_WORDS  3712                       // u,v,hrw,htw,idr,idt(1536) + vh(128) + part(2048)
#define SCAP_HALF ((SMEM_A_WORDS - AUX_A_WORDS) * 2)   // 48896 halves for S

// ---- fallback path (fp32 S, 1 CTA/SM) = R11 ----
#define SINK_SMEM_BYTES 230400
#define SINK_SMEM_WORDS (SINK_SMEM_BYTES / 4)
#define AUX_WORDS 3584
#define SCAP_F32 (SINK_SMEM_WORDS - AUX_WORDS)  // 54016 floats for S

// ---------------- scratch (static device globals; no allocation) ----------------
__device__ float    g_oklab[2][4 * 3 * NPIX];
__device__ unsigned g_mm[12];
__device__ float    g_K[NB * NB];
__device__ float    g_KC[NB * NB];
__device__ int      g_scnt[2][PCOUNT];
__device__ int      g_sidx[2][PCOUNT][256];
__device__ float    g_sw[2][PCOUNT][256];
__device__ float    g_emd[PCOUNT];

// ---------------- helpers ----------------
__device__ __forceinline__ unsigned fenc(float f) {
    unsigned u = __float_as_uint(f);
    return (u & 0x80000000u) ? ~u : (u | 0x80000000u);
}
__device__ __forceinline__ float fdec(unsigned u) {
    return __uint_as_float((u & 0x80000000u) ? (u ^ 0x80000000u) : ~u);
}
__device__ __forceinline__ float srgb_lin(float x) {
    x = fminf(fmaxf(x, 0.0f), 1.0f);
    return (x <= 0.04045f) ? x * (1.0f / 12.92f)
                           : powf((x + 0.055f) * (1.0f / 1.055f), 2.4f);
}
__device__ __forceinline__ void get_lohi(int img, float* lo, float* hi) {
#pragma unroll
    for (int c = 0; c < 3; c++) {
        float l = fdec(g_mm[img * 3 + c]) - 0.01f;
        float h = fdec(g_mm[6 + img * 3 + c]) + 0.01f;
        if (h - l < 1e-4f) { l -= 0.05f; h += 0.05f; }
        lo[c] = l; hi[c] = h;
    }
}

// ---------------- init: minmax sentinels ----------------
__global__ void init_kernel() {
    int idx = threadIdx.x;
    if (idx < 6) g_mm[idx] = 0xFFFFFFFFu;
    else if (idx < 12) g_mm[idx] = 0u;
}

// ---------------- sRGB -> OKLab + per-channel global min/max ----------------
__global__ void oklab_kernel(const float* __restrict__ ref, const float* __restrict__ tgt) {
    const int img = blockIdx.y;
    const float* __restrict__ in = img ? tgt : ref;
    float* __restrict__ outp = g_oklab[img];
    float mn0 = 1e30f, mn1 = 1e30f, mn2 = 1e30f;
    float mx0 = -1e30f, mx1 = -1e30f, mx2 = -1e30f;

    for (int idx = blockIdx.x * blockDim.x + threadIdx.x; idx < 4 * NPIX;
         idx += gridDim.x * blockDim.x) {
        int b = idx >> 16;
        int hw = idx & 65535;
        int base = b * 3 * NPIX + hw;
        float r  = srgb_lin(in[base]);
        float g  = srgb_lin(in[base + NPIX]);
        float bl = srgb_lin(in[base + 2 * NPIX]);
        float l = 0.4122214708f * r + 0.5363325363f * g + 0.0514459929f * bl;
        float m = 0.2119034982f * r + 0.6806995451f * g + 0.1073969566f * bl;
        float s = 0.0883024619f * r + 0.2817188376f * g + 0.6299787005f * bl;
        l = fmaxf(l, 0.0f); m = fmaxf(m, 0.0f); s = fmaxf(s, 0.0f);
        float lg = (l > 0.0f) ? cbrtf(fmaxf(l, 1e-12f)) : 0.0f;
        float mg = (m > 0.0f) ? cbrtf(fmaxf(m, 1e-12f)) : 0.0f;
        float sg = (s > 0.0f) ? cbrtf(fmaxf(s, 1e-12f)) : 0.0f;
        float L = 0.2104542553f * lg + 0.793617785f  * mg - 0.0040720468f * sg;
        float A = 1.9779984951f * lg - 2.428592205f  * mg + 0.4505937099f * sg;
        float B = 0.0259040371f * lg + 0.7827717662f * mg - 0.808675766f  * sg;
        outp[base] = L; outp[base + NPIX] = A; outp[base + 2 * NPIX] = B;
        mn0 = fminf(mn0, L); mx0 = fmaxf(mx0, L);
        mn1 = fminf(mn1, A); mx1 = fmaxf(mx1, A);
        mn2 = fminf(mn2, B); mx2 = fmaxf(mx2, B);
    }
#pragma unroll
    for (int o = 16; o > 0; o >>= 1) {
        mn0 = fminf(mn0, __shfl_down_sync(0xffffffffu, mn0, o));
        mn1 = fminf(mn1, __shfl_down_sync(0xffffffffu, mn1, o));
        mn2 = fminf(mn2, __shfl_down_sync(0xffffffffu, mn2, o));
        mx0 = fmaxf(mx0, __shfl_down_sync(0xffffffffu, mx0, o));
        mx1 = fmaxf(mx1, __shfl_down_sync(0xffffffffu, mx1, o));
        mx2 = fmaxf(mx2, __shfl_down_sync(0xffffffffu, mx2, o));
    }
    if ((threadIdx.x & 31) == 0) {
        atomicMin(&g_mm[img * 3 + 0], fenc(mn0));
        atomicMin(&g_mm[img * 3 + 1], fenc(mn1));
        atomicMin(&g_mm[img * 3 + 2], fenc(mn2));
        atomicMax(&g_mm[6 + img * 3 + 0], fenc(mx0));
        atomicMax(&g_mm[6 + img * 3 + 1], fenc(mx1));
        atomicMax(&g_mm[6 + img * 3 + 2], fenc(mx2));
    }
}

// ---------------- build K = exp(-cost/REG) and KC = K*cost on averaged grid ----------------
__global__ void buildK_kernel() {
    int i = blockIdx.x, j = threadIdx.x;
    float lor[3], hir[3], lot[3], hit[3];
    get_lohi(0, lor, hir);
    get_lohi(1, lot, hit);
    float step[3];
#pragma unroll
    for (int c = 0; c < 3; c++)
        step[c] = ((hir[c] - lor[c]) + (hit[c] - lot[c])) * 0.5f * 0.125f;
    int i0 = i >> 6, i1 = (i >> 3) & 7, i2 = i & 7;
    int j0 = j >> 6, j1 = (j >> 3) & 7, j2 = j & 7;
    float d0 = step[0] * (float)(i0 - j0);
    float d1 = step[1] * (float)(i1 - j1);
    float d2 = step[2] * (float)(i2 - j2);
    float dd = d0 * d0 + d1 * d1 + d2 * d2;
    float cost = (dd > 0.0f) ? sqrtf(dd) : 0.0f;
    float Kv = expf(-cost * 10.0f);        // REG = 0.1
    g_K[i * NB + j]  = Kv;
    g_KC[i * NB + j] = Kv * cost;
}

// ---------------- per-patch histograms + deterministic support-list extraction --------
__global__ void hist_kernel() {
    const int img = blockIdx.y, p = blockIdx.x, t = threadIdx.x;   // 256 threads
    __shared__ float h[NB];
    __shared__ int sca[NB], scb[NB];
    __shared__ float lo_s[3], inv_s[3];
    if (t == 0) {
        float lo[3], hi[3];
        get_lohi(img, lo, hi);
#pragma unroll
        for (int c = 0; c < 3; c++) { lo_s[c] = lo[c]; inv_s[c] = 8.0f / (hi[c] - lo[c]); }
    }
    h[t] = 0.0f; h[t + 256] = 0.0f;
    __syncthreads();

    int b = p >> 8, ph = (p >> 4) & 15, pw = p & 15;
    int py = t >> 4, px = t & 15;
    int hh = (ph << 4) + py, ww = (pw << 4) + px;
    int base = b * 3 * NPIX + hh * 256 + ww;
    const float* ok = g_oklab[img];
    float xL = ok[base], xA = ok[base + NPIX], xB = ok[base + 2 * NPIX];
    int i0 = (int)floorf((xL - lo_s[0]) * inv_s[0]); i0 = min(7, max(0, i0));
    int i1 = (int)floorf((xA - lo_s[1]) * inv_s[1]); i1 = min(7, max(0, i1));
    int i2 = (int)floorf((xB - lo_s[2]) * inv_s[2]); i2 = min(7, max(0, i2));
    atomicAdd(&h[(i0 << 6) | (i1 << 3) | i2], 1.0f);
    __syncthreads();

    // inclusive prefix scan of occupancy flags over 512 bins (Hillis-Steele, ping-pong)
    sca[t] = (h[t] > 0.0f) ? 1 : 0;
    sca[t + 256] = (h[t + 256] > 0.0f) ? 1 : 0;
    __syncthreads();
    int* src = sca; int* dst = scb;
    for (int off = 1; off < NB; off <<= 1) {
#pragma unroll
        for (int q = 0; q < 2; q++) {
            int i = t + q * 256;
            dst[i] = src[i] + ((i >= off) ? src[i - off] : 0);
        }
        __syncthreads();
        int* tmp = src; src = dst; dst = tmp;
    }

#pragma unroll
    for (int q = 0; q < 2; q++) {
        int i = t + q * 256;
        if (h[i] > 0.0f) {
            int pos = src[i] - 1;
            g_sidx[img][p][pos] = i;
            g_sw[img][p][pos]   = h[i] * (1.0f / 256.0f);
        }
    }
    if (t == 0) g_scnt[img][p] = src[NB - 1];
}

// =============== FAST sinkhorn: half S (LDS.128 rows), reg-cached v, 2 CTAs/SM ========
// thread `lane` owns columns [8*lane, 8*lane+8); S rows zero-padded to pad8
__global__ void __launch_bounds__(256) sink_a() {
    extern __shared__ float sm[];
    const int p = blockIdx.x;
    const int sr = g_scnt[0][p], st = g_scnt[1][p];
    const int pad8 = (st + 7) & ~7;
    if ((long)sr * pad8 > SCAP_HALF) return;        // fallback pass handles

    float*  u   = sm;
    float*  v   = sm + 256;
    float*  hrw = sm + 512;
    float*  htw = sm + 768;
    int*    idr = (int*)(sm + 1024);
    int*    idt = (int*)(sm + 1280);
    __half* vh  = (__half*)(sm + 1536);             // 256 halves (zero-padded)
    float*  part = sm + 1664;                       // [8][256]
    __half* S   = (__half*)(sm + AUX_A_WORDS);

    const int tid = threadIdx.x, lane = tid & 31, w = tid >> 5;   // 8 warps
    const int jb = lane * 8;                         // thread's column base
    const bool act = (jb < pad8);

    if (tid < sr) { idr[tid] = g_sidx[0][p][tid]; hrw[tid] = g_sw[0][p][tid]; u[tid] = 1.0f; }
    if (tid < st) { idt[tid] = g_sidx[1][p][tid]; htw[tid] = g_sw[1][p][tid]; }
    vh[tid] = __float2half(0.0f);                    // padding stays 0 forever
    __syncthreads();

    // gather S[i][j] = half(K[idr[i], idt[j]]), zero-fill [st, pad8)
    for (int i = w; i < sr; i += 8) {
        const float* Krow = g_K + (size_t)idr[i] * NB;
        for (int j = lane; j < pad8; j += 32)
            S[i * pad8 + j] = __float2half((j < st) ? Krow[idt[j]] : 0.0f);
    }
    __syncthreads();

    const int i0c = (sr * w) >> 3, i1c = (sr * (w + 1)) >> 3;   // v-update row chunk
    float* pw = part + w * 256;

    for (int it = 0; it < 20; it++) {
        // ---- v_j = ht_j / (sum_i u_i S[i][j] + eps): u-broadcast, 1 LDS.128/row ----
        {
            float2 a0 = {0.f,0.f}, a1 = {0.f,0.f}, a2 = {0.f,0.f}, a3 = {0.f,0.f};
            if (act) {
                for (int i = i0c; i < i1c; i++) {
                    float ui = u[i];                      // warp-uniform broadcast
                    uint4 sv = *(const uint4*)(S + i * pad8 + jb);
                    const __half2* hp = (const __half2*)&sv;
                    float2 s0 = __half22float2(hp[0]), s1 = __half22float2(hp[1]);
                    float2 s2 = __half22float2(hp[2]), s3 = __half22float2(hp[3]);
                    a0.x += ui * s0.x; a0.y += ui * s0.y;
                    a1.x += ui * s1.x; a1.y += ui * s1.y;
                    a2.x += ui * s2.x; a2.y += ui * s2.y;
                    a3.x += ui * s3.x; a3.y += ui * s3.y;
                }
                *(float4*)(pw + jb)     = make_float4(a0.x, a0.y, a1.x, a1.y);
                *(float4*)(pw + jb + 4) = make_float4(a2.x, a2.y, a3.x, a3.y);
            }
        }
        __syncthreads();
        if (tid < st) {
            float d = part[tid] + part[256 + tid] + part[512 + tid] + part[768 + tid]
                    + part[1024 + tid] + part[1280 + tid] + part[1536 + tid] + part[1792 + tid];
            float val = __fdividef(htw[tid], d + SINK_EPS);
            v[tid] = val;
            vh[tid] = __float2half(val);
        }
        __syncthreads();
        // ---- u_i = hr_i / (sum_j v_j S[i][j] + eps): reg-cached v, warp-per-row ----
        {
            float vr0x=0.f,vr0y=0.f,vr1x=0.f,vr1y=0.f,vr2x=0.f,vr2y=0.f,vr3x=0.f,vr3y=0.f;
            if (act) {
                uint4 vv = *(const uint4*)(vh + jb);
                const __half2* hp = (const __half2*)&vv;
                float2 t0 = __half22float2(hp[0]), t1 = __half22float2(hp[1]);
                float2 t2 = __half22float2(hp[2]), t3 = __half22float2(hp[3]);
                vr0x = t0.x; vr0y = t0.y; vr1x = t1.x; vr1y = t1.y;
                vr2x = t2.x; vr2y = t2.y; vr3x = t3.x; vr3y = t3.y;
            }
            for (int i = w; i < sr; i += 8) {
                float acc = 0.0f;
                if (act) {
                    uint4 sv = *(const uint4*)(S + i * pad8 + jb);
                    const __half2* hp = (const __half2*)&sv;
                    float2 s0 = __half22float2(hp[0]), s1 = __half22float2(hp[1]);
                    float2 s2 = __half22float2(hp[2]), s3 = __half22float2(hp[3]);
                    acc = s0.x * vr0x + s0.y * vr0y + s1.x * vr1x + s1.y * vr1y
                        + s2.x * vr2x + s2.y * vr2y + s3.x * vr3x + s3.y * vr3y;
                }
#pragma unroll
                for (int o = 16; o > 0; o >>= 1)
                    acc += __shfl_xor_sync(0xffffffffu, acc, o);
                if (lane == 0) u[i] = __fdividef(hrw[i], acc + SINK_EPS);
            }
        }
        __syncthreads();
    }

    // ---- re-gather S <- KC; emd = sum_j v_j * (sum_i u_i KC_ij) ----
    for (int i = w; i < sr; i += 8) {
        const float* Crow = g_KC + (size_t)idr[i] * NB;
        for (int j = lane; j < pad8; j += 32)
            S[i * pad8 + j] = __float2half((j < st) ? Crow[idt[j]] : 0.0f);
    }
    __syncthreads();
    {
        float2 a0 = {0.f,0.f}, a1 = {0.f,0.f}, a2 = {0.f,0.f}, a3 = {0.f,0.f};
        if (act) {
            for (int i = i0c; i < i1c; i++) {
                float ui = u[i];
                uint4 sv = *(const uint4*)(S + i * pad8 + jb);
                const __half2* hp = (const __half2*)&sv;
                float2 s0 = __half22float2(hp[0]), s1 = __half22float2(hp[1]);
                float2 s2 = __half22float2(hp[2]), s3 = __half22float2(hp[3]);
                a0.x += ui * s0.x; a0.y += ui * s0.y;
                a1.x += ui * s1.x; a1.y += ui * s1.y;
                a2.x += ui * s2.x; a2.y += ui * s2.y;
                a3.x += ui * s3.x; a3.y += ui * s3.y;
            }
            *(float4*)(pw + jb)     = make_float4(a0.x, a0.y, a1.x, a1.y);
            *(float4*)(pw + jb + 4) = make_float4(a2.x, a2.y, a3.x, a3.y);
        }
    }
    __syncthreads();
    float e = 0.0f;
    if (tid < st) {
        float d = part[tid] + part[256 + tid] + part[512 + tid] + part[768 + tid]
                + part[1024 + tid] + part[1280 + tid] + part[1536 + tid] + part[1792 + tid];
        e = v[tid] * d;
    }
    __syncthreads();
    part[tid] = e;
    __syncthreads();
    for (int o = 128; o > 0; o >>= 1) {
        if (tid < o) part[tid] += part[tid + o];
        __syncthreads();
    }
    if (tid == 0) {
        float r = part[0];
        g_emd[p] = isfinite(r) ? r : 0.0f;
    }
}

// =============== FALLBACK sinkhorn (R11 fp32 path) for oversized supports =============
template <typename T>
__device__ void sink_body(float* sm, int p, int sr, int st, int pad) {
    float* u   = sm;
    float* v   = sm + 256;
    float* hrw = sm + 512;
    float* htw = sm + 768;
    int*   idr = (int*)(sm + 1024);
    int*   idt = (int*)(sm + 1280);
    float* part = sm + 1536;
    T*     S   = (T*)(sm + AUX_WORDS);

    const int tid = threadIdx.x, lane = tid & 31, w = tid >> 5;

    if (tid < sr) { idr[tid] = g_sidx[0][p][tid]; hrw[tid] = g_sw[0][p][tid]; u[tid] = 1.0f; }
    if (tid < st) { idt[tid] = g_sidx[1][p][tid]; htw[tid] = g_sw[1][p][tid]; }
    __syncthreads();

    for (int i = w; i < sr; i += 8) {
        const float* Krow = g_K + (size_t)idr[i] * NB;
        for (int j = lane; j < st; j += 32) S[i * pad + j] = (T)Krow[idt[j]];
    }
    __syncthreads();

    const int iw0 = (sr * w) >> 3, iw1 = (sr * (w + 1)) >> 3;
    const int jw0 = (st * w) >> 3, jw1 = (st * (w + 1)) >> 3;

    for (int it = 0; it < 20; it++) {
        for (int j = lane; j < st; j += 32) {
            float acc = 0.0f;
            for (int i = iw0; i < iw1; i++) acc += u[i] * (float)S[i * pad + j];
            part[w * 256 + j] = acc;
        }
        __syncthreads();
        if (tid < st) {
            float d = part[tid] + part[256 + tid] + part[512 + tid] + part[768 + tid]
                    + part[1024 + tid] + part[1280 + tid] + part[1536 + tid] + part[1792 + tid];
            v[tid] = __fdividef(htw[tid], d + SINK_EPS);
        }
        __syncthreads();
        for (int i = lane; i < sr; i += 32) {
            float acc = 0.0f;
            for (int j = jw0; j < jw1; j++) acc += v[j] * (float)S[i * pad + j];
            part[w * 256 + i] = acc;
        }
        __syncthreads();
        if (tid < sr) {
            float d = part[tid] + part[256 + tid] + part[512 + tid] + part[768 + tid]
                    + part[1024 + tid] + part[1280 + tid] + part[1536 + tid] + part[1792 + tid];
            u[tid] = __fdividef(hrw[tid], d + SINK_EPS);
        }
        __syncthreads();
    }

    for (int i = w; i < sr; i += 8) {
        const float* Crow = g_KC + (size_t)idr[i] * NB;
        for (int j = lane; j < st; j += 32) S[i * pad + j] = (T)Crow[idt[j]];
    }
    __syncthreads();
    for (int j = lane; j < st; j += 32) {
        float acc = 0.0f;
        for (int i = iw0; i < iw1; i++) acc += u[i] * (float)S[i * pad + j];
        part[w * 256 + j] = acc;
    }
    __syncthreads();
    float e = 0.0f;
    if (tid < st) {
        float d = part[tid] + part[256 + tid] + part[512 + tid] + part[768 + tid]
                + part[1024 + tid] + part[1280 + tid] + part[1536 + tid] + part[1792 + tid];
        e = v[tid] * d;
    }
    __syncthreads();
    part[tid] = e;
    __syncthreads();
    for (int o = 128; o > 0; o >>= 1) {
        if (tid < o) part[tid] += part[tid + o];
        __syncthreads();
    }
    if (tid == 0) {
        float r = part[0];
        g_emd[p] = isfinite(r) ? r : 0.0f;
    }
}

__global__ void __launch_bounds__(256) sink_b() {
    extern __shared__ float sm[];
    const int p = blockIdx.x;
    const int sr = g_scnt[0][p], st = g_scnt[1][p];
    const int pad8 = (st + 7) & ~7;
    if ((long)sr * pad8 <= SCAP_HALF) return;       // already done by sink_a
    const int pad = st | 1;
    if ((long)sr * pad <= SCAP_F32) sink_body<float>(sm, p, sr, st, pad);
    else                            sink_body<__half>(sm, p, sr, st, pad);
}

// ---------------- half-pixel bilinear upsample 16x16 -> 256x256 ----------------
__global__ void upsample_kernel(float* __restrict__ out) {
    int idx = blockIdx.x * blockDim.x + threadIdx.x;
    if (idx >= 4 * NPIX) return;
    int b = idx >> 16, y = (idx >> 8) & 255, x = idx & 255;
    float fy = (y + 0.5f) * 0.0625f - 0.5f;
    float fx = (x + 0.5f) * 0.0625f - 0.5f;
    int y0 = (int)floorf(fy); float wy = fy - (float)y0;
    int x0 = (int)floorf(fx); float wx = fx - (float)x0;
    int y0c = min(15, max(0, y0)), y1c = min(15, max(0, y0 + 1));
    int x0c = min(15, max(0, x0)), x1c = min(15, max(0, x0 + 1));
    const float* e = g_emd + b * 256;
    float v00 = e[y0c * 16 + x0c], v01 = e[y0c * 16 + x1c];
    float v10 = e[y1c * 16 + x0c], v11 = e[y1c * 16 + x1c];
    v00 = isfinite(v00) ? v00 : 0.0f;
    v01 = isfinite(v01) ? v01 : 0.0f;
    v10 = isfinite(v10) ? v10 : 0.0f;
    v11 = isfinite(v11) ? v11 : 0.0f;
    float t0 = v00 + (v01 - v00) * wx;
    float t1 = v10 + (v11 - v10) * wx;
    out[idx] = t0 + (t1 - t0) * wy;
}

// ---------------- launcher ----------------
extern "C" void kernel_launch(void* const* d_in, const int* in_sizes, int n_in,
                              void* d_out, int out_size) {
    (void)in_sizes; (void)n_in; (void)out_size;
    const float* ref = (const float*)d_in[0];
    const float* tgt = (const float*)d_in[1];
    float* out = (float*)d_out;

    static int smem_set = 0;
    if (!smem_set) {
        cudaFuncSetAttribute(sink_a, cudaFuncAttributeMaxDynamicSharedMemorySize,
                             SMEM_A_BYTES);
        cudaFuncSetAttribute(sink_b, cudaFuncAttributeMaxDynamicSharedMemorySize,
                             SINK_SMEM_BYTES);
        smem_set = 1;
    }

    init_kernel<<<1, 32>>>();
    oklab_kernel<<<dim3(256, 2), 256>>>(ref, tgt);
    buildK_kernel<<<NB, NB>>>();
    hist_kernel<<<dim3(PCOUNT, 2), 256>>>();
    sink_a<<<PCOUNT, 256, SMEM_A_BYTES>>>();
    sink_b<<<PCOUNT, 256, SINK_SMEM_BYTES>>>();
    upsample_kernel<<<(4 * NPIX + 255) / 256, 256>>>(out);
}